// round 12
// baseline (speedup 1.0000x reference)
#include <cuda_runtime.h>
#include <cstdint>

// GaussianKDE via legacy mma.sync tf32 (single pass) + INTERLEAVED exp epilogue.
// R11 base (205us) with the epilogue of the previous 64-col half issued one
// chunk per k-step inside the current half's MMA loop (hides MUFU under HMMA).
// Scalar LDS.32 fragment loads (no PERM - PERM was the R8/R9 ALU bloat).
// bs uses a 4-slot ring so the interleaved epilogue never races the prefetch.
// out[q] = (norm/N) * a[q] * sum_n b[n] * exp2((log2e*f_q) . x_n)

#define DCONST 64
#define QCAP   4096
#define NCAP   50048        // 391 * 128
#define QTILE  128
#define NTILE  128
#define NCHUNK 9            // 32 q-tiles * 9 = 288 blocks ~= 2 waves * 148 SMs
#define XS     68           // padded smem row stride in floats (bank-conflict-free)
#define LOG2E  1.44269504088896340736f

#define OFF_FHI 0
#define TILE_B  (128 * XS * 4)          // 34816 bytes per 128x64 padded tile
#define OFF_X   (OFF_FHI + TILE_B)      // 2 buffers
#define OFF_BS  (OFF_X + 2 * TILE_B)    // bs ring: 4 slots x 128 floats
#define OFF_RED (OFF_BS + 2048)         // red[256] floats
#define SMEM_TOTAL (OFF_RED + 1024)

__device__ float g_fhi[QCAP * DCONST];   // tf32(log2e * f)
__device__ float g_a[QCAP];
__device__ float g_xhi[NCAP * DCONST];   // tf32(x)
__device__ float g_b[NCAP];

// ---------------------------------------------------------------------------
__device__ __forceinline__ uint32_t smem_u32(const void* p) {
    uint32_t a;
    asm("{ .reg .u64 t; cvta.to.shared.u64 t, %1; cvt.u32.u64 %0, t; }"
        : "=r"(a) : "l"(p));
    return a;
}
__device__ __forceinline__ void cp16(uint32_t dst, const void* src) {
    asm volatile("cp.async.cg.shared.global [%0], [%1], 16;"
                 :: "r"(dst), "l"(src) : "memory");
}
__device__ __forceinline__ void mma8(float* d, const uint32_t* a,
                                     uint32_t b0, uint32_t b1) {
    asm volatile("mma.sync.aligned.m16n8k8.row.col.f32.tf32.tf32.f32 "
                 "{%0,%1,%2,%3}, {%4,%5,%6,%7}, {%8,%9}, {%0,%1,%2,%3};"
                 : "+f"(d[0]), "+f"(d[1]), "+f"(d[2]), "+f"(d[3])
                 : "r"(a[0]), "r"(a[1]), "r"(a[2]), "r"(a[3]),
                   "r"(b0), "r"(b1));
}
__device__ __forceinline__ uint32_t to_tf32_bits(float x) {
    uint32_t r;
    asm("cvt.rna.tf32.f32 %0, %1;" : "=r"(r) : "f"(x));
    return r;
}
__device__ __forceinline__ float ex2(float x) {
    float r;
    asm("ex2.approx.f32 %0, %1;" : "=f"(r) : "f"(x));
    return r;
}

// ---------------------------------------------------------------------------
// Fused prep: blocks [0, FB) do the F side, blocks [FB, ...) the X side.
__global__ void prep_kernel(const float* __restrict__ feat,
                            const float* __restrict__ bw,
                            const float* __restrict__ ds,
                            float* __restrict__ out, int Q, int N, int FB) {
    int tid = threadIdx.x;
    if ((int)blockIdx.x < FB) {
        __shared__ float bws[DCONST][DCONST];
        for (int i = tid; i < DCONST * DCONST; i += 256)
            bws[i / DCONST][i % DCONST] = bw[i];
        __syncthreads();
        int q = blockIdx.x * 256 + tid;
        if (q >= Q) return;

        float r[DCONST];
        const float4* fr = (const float4*)(feat + (size_t)q * DCONST);
#pragma unroll
        for (int v = 0; v < DCONST / 4; v++) {
            float4 t = fr[v];
            r[4 * v + 0] = t.x; r[4 * v + 1] = t.y;
            r[4 * v + 2] = t.z; r[4 * v + 3] = t.w;
        }
        float f2 = 0.0f;
#pragma unroll 4
        for (int d = 0; d < DCONST; d++) {
            float acc = 0.0f;
#pragma unroll
            for (int k = 0; k < DCONST; k++) acc = fmaf(r[k], bws[k][d], acc);
            g_fhi[(size_t)q * DCONST + d] =
                __uint_as_float(to_tf32_bits(acc * LOG2E));
            f2 = fmaf(acc, acc, f2);
        }
        g_a[q] = expf(-0.5f * f2);
        out[q] = 0.0f;
    } else {
        int n = (blockIdx.x - FB) * 256 + tid;
        if (n >= NCAP) return;
        if (n < N) {
            float x2 = 0.0f;
            const float4* r4 = (const float4*)(ds + (size_t)n * DCONST);
#pragma unroll
            for (int v = 0; v < DCONST / 4; v++) {
                float4 t = r4[v];
                float e[4] = {t.x, t.y, t.z, t.w};
#pragma unroll
                for (int j = 0; j < 4; j++) {
                    g_xhi[(size_t)n * DCONST + 4 * v + j] =
                        __uint_as_float(to_tf32_bits(e[j]));
                    x2 = fmaf(e[j], e[j], x2);
                }
            }
            g_b[n] = expf(-0.5f * x2);
        } else {
#pragma unroll
            for (int v = 0; v < DCONST / 4; v++)
                *(float4*)(g_xhi + (size_t)n * DCONST + 4 * v) =
                    make_float4(0, 0, 0, 0);
            g_b[n] = 0.0f;
        }
    }
}

// ---------------------------------------------------------------------------
// Main kernel: 128(Q) x 128(N) tile per block, 256 threads (8 warps).
// Warp = 32(Q) x 64(N): wq = wid>>1, wn = wid&1; each tile = two 32-col
// halves (accA/accB). Epilogue of the previous half is issued one chunk per
// k-step inside the current half's MMA loop.
__global__ __launch_bounds__(256, 1) void kde_mma_kernel(
    const float* __restrict__ norm, float* __restrict__ out,
    int Q, int N, int NT) {
    extern __shared__ char smem[];
    const uint32_t sb = smem_u32(smem);
    const float* fh = (const float*)(smem + OFF_FHI);
    const int tid = threadIdx.x, lane = tid & 31, wid = tid >> 5;
    const int wq = wid >> 1, wn = wid & 1;
    const int q0 = blockIdx.x * QTILE;
    const int t0 = (blockIdx.y * NT) / NCHUNK;
    const int t1 = ((blockIdx.y + 1) * NT) / NCHUNK;
    const int cnt = t1 - t0;

    // Stage F tile and first X tile via cp.async (one group). bs -> slot 0.
#pragma unroll
    for (int i = 0; i < 8; i++) {
        int e = tid + (i << 8);
        int row = e >> 4, c = e & 15;
        cp16(sb + OFF_FHI + row * (XS * 4) + c * 16,
             g_fhi + (size_t)(q0 + row) * DCONST + c * 4);
    }
    {
        int n0 = t0 * NTILE;
#pragma unroll
        for (int i = 0; i < 8; i++) {
            int e = tid + (i << 8);
            int row = e >> 4, c = e & 15;
            cp16(sb + OFF_X + row * (XS * 4) + c * 16,
                 g_xhi + (size_t)(n0 + row) * DCONST + c * 4);
        }
        if (tid < 32) cp16(sb + OFF_BS + tid * 16, g_b + n0 + tid * 4);
    }
    asm volatile("cp.async.commit_group;");

    const int rA = wq * 32 + (lane >> 2);
    const int cA = lane & 3;
    const int colB = lane >> 2;

    uint32_t ah[2][8][4];     // A fragments, all k-steps, register-resident
    float accA[2][4][4], accB[2][4][4];
    float racc[2][2] = {{0.f, 0.f}, {0.f, 0.f}};
    bool a_loaded = false;

    for (int j = 0; j < cnt; j++) {
        const int b = j & 1;
        if (j + 1 < cnt) {
            // Prefetch next X tile into buffer b^1; bs -> slot (j+1)&3.
            int n0 = (t0 + j + 1) * NTILE;
            int bb = (j + 1) & 1;
#pragma unroll
            for (int i = 0; i < 8; i++) {
                int e = tid + (i << 8);
                int row = e >> 4, c = e & 15;
                cp16(sb + OFF_X + bb * TILE_B + row * (XS * 4) + c * 16,
                     g_xhi + (size_t)(n0 + row) * DCONST + c * 4);
            }
            if (tid < 32)
                cp16(sb + OFF_BS + ((j + 1) & 3) * 512 + tid * 16, g_b + n0 + tid * 4);
            asm volatile("cp.async.commit_group;");
            asm volatile("cp.async.wait_group 1;");
        } else {
            asm volatile("cp.async.wait_group 0;");
        }
        __syncthreads();

        if (!a_loaded) {    // F tile resident after first wait
            a_loaded = true;
#pragma unroll
            for (int qs = 0; qs < 2; qs++)
#pragma unroll
                for (int kk = 0; kk < 8; kk++) {
                    const float* p = fh + (rA + qs * 16) * XS + kk * 8 + cA;
                    ah[qs][kk][0] = __float_as_uint(p[0]);
                    ah[qs][kk][1] = __float_as_uint(p[8 * XS]);
                    ah[qs][kk][2] = __float_as_uint(p[4]);
                    ah[qs][kk][3] = __float_as_uint(p[8 * XS + 4]);
                }
        }

        const float* xp = (const float*)(smem + OFF_X + b * TILE_B);
        const float* bs_prev = (const float*)(smem + OFF_BS + ((j - 1) & 3) * 512);
        const float* bs_cur  = (const float*)(smem + OFF_BS + (j & 3) * 512);

        // ---- half0 -> accA (n cols [0,32)); epilogue of accB (prev tile h1)
#pragma unroll
        for (int qs = 0; qs < 2; qs++)
#pragma unroll
            for (int ns = 0; ns < 4; ns++)
#pragma unroll
                for (int i = 0; i < 4; i++) accA[qs][ns][i] = 0.f;

#pragma unroll
        for (int kk = 0; kk < 8; kk++) {
#pragma unroll
            for (int ns = 0; ns < 4; ns++) {
                const float* pb = xp + (wn * 64 + ns * 8 + colB) * XS + kk * 8 + cA;
                uint32_t b0 = __float_as_uint(pb[0]);
                uint32_t b1 = __float_as_uint(pb[4]);
                mma8(accA[0][ns], ah[0][kk], b0, b1);
                mma8(accA[1][ns], ah[1][kk], b0, b1);
            }
            if (j > 0) {    // one epilogue chunk of the previous tile's half1
                const int eqs = kk >> 2, ens = kk & 3;
                float2 bv = *(const float2*)(bs_prev + wn * 64 + 32 + ens * 8 + 2 * cA);
                racc[eqs][0] += bv.x * ex2(accB[eqs][ens][0]) +
                                bv.y * ex2(accB[eqs][ens][1]);
                racc[eqs][1] += bv.x * ex2(accB[eqs][ens][2]) +
                                bv.y * ex2(accB[eqs][ens][3]);
            }
        }

        // ---- half1 -> accB (n cols [32,64)); epilogue of accA (this tile h0)
#pragma unroll
        for (int qs = 0; qs < 2; qs++)
#pragma unroll
            for (int ns = 0; ns < 4; ns++)
#pragma unroll
                for (int i = 0; i < 4; i++) accB[qs][ns][i] = 0.f;

#pragma unroll
        for (int kk = 0; kk < 8; kk++) {
#pragma unroll
            for (int ns = 0; ns < 4; ns++) {
                const float* pb = xp + (wn * 64 + 32 + ns * 8 + colB) * XS + kk * 8 + cA;
                uint32_t b0 = __float_as_uint(pb[0]);
                uint32_t b1 = __float_as_uint(pb[4]);
                mma8(accB[0][ns], ah[0][kk], b0, b1);
                mma8(accB[1][ns], ah[1][kk], b0, b1);
            }
            {
                const int eqs = kk >> 2, ens = kk & 3;
                float2 bv = *(const float2*)(bs_cur + wn * 64 + ens * 8 + 2 * cA);
                racc[eqs][0] += bv.x * ex2(accA[eqs][ens][0]) +
                                bv.y * ex2(accA[eqs][ens][1]);
                racc[eqs][1] += bv.x * ex2(accA[eqs][ens][2]) +
                                bv.y * ex2(accA[eqs][ens][3]);
            }
        }
        __syncthreads();   // X[b] reads done before next iter's prefetch reuse
    }

    // Tail: epilogue of the last tile's half1 (accB), bs slot (cnt-1)&3.
    {
        const float* bs_last = (const float*)(smem + OFF_BS + ((cnt - 1) & 3) * 512);
#pragma unroll
        for (int qs = 0; qs < 2; qs++)
#pragma unroll
            for (int ns = 0; ns < 4; ns++) {
                float2 bv = *(const float2*)(bs_last + wn * 64 + 32 + ns * 8 + 2 * cA);
                racc[qs][0] += bv.x * ex2(accB[qs][ns][0]) +
                               bv.y * ex2(accB[qs][ns][1]);
                racc[qs][1] += bv.x * ex2(accB[qs][ns][2]) +
                               bv.y * ex2(accB[qs][ns][3]);
            }
    }

    // Reduce across the 4 lanes sharing each output row.
#pragma unroll
    for (int qs = 0; qs < 2; qs++)
#pragma unroll
        for (int h = 0; h < 2; h++) {
            float v = racc[qs][h];
            v += __shfl_xor_sync(0xffffffff, v, 1);
            v += __shfl_xor_sync(0xffffffff, v, 2);
            racc[qs][h] = v;
        }
    __syncthreads();
    float* red = (float*)(smem + OFF_RED);
    if ((lane & 3) == 0) {
        int r = lane >> 2;
#pragma unroll
        for (int qs = 0; qs < 2; qs++)
#pragma unroll
            for (int h = 0; h < 2; h++)
                red[wn * 128 + wq * 32 + qs * 16 + h * 8 + r] = racc[qs][h];
    }
    __syncthreads();
    if (tid < 128) {
        int q = q0 + tid;
        if (q < Q) {
            float s = red[tid] + red[128 + tid];
            atomicAdd(&out[q], s * g_a[q] * (__ldg(norm) / (float)N));
        }
    }
}

// ---------------------------------------------------------------------------
extern "C" void kernel_launch(void* const* d_in, const int* in_sizes, int n_in,
                              void* d_out, int out_size) {
    const float* features = (const float*)d_in[0];
    const float* bw       = (const float*)d_in[1];
    const float* dataset  = (const float*)d_in[2];
    const float* norm     = (const float*)d_in[3];

    int Q = in_sizes[0] / DCONST;
    int N = in_sizes[2] / DCONST;
    int NT = (N + NTILE - 1) / NTILE;
    float* out = (float*)d_out;

    cudaFuncSetAttribute(kde_mma_kernel,
                         cudaFuncAttributeMaxDynamicSharedMemorySize, SMEM_TOTAL);

    int FB = (Q + 255) / 256;
    int XB = (NCAP + 255) / 256;
    prep_kernel<<<FB + XB, 256>>>(features, bw, dataset, out, Q, N, FB);

    dim3 grid((Q + QTILE - 1) / QTILE, NCHUNK);
    kde_mma_kernel<<<grid, 256, SMEM_TOTAL>>>(norm, out, Q, N, NT);
}